// round 7
// baseline (speedup 1.0000x reference)
#include <cuda_runtime.h>
#include <cuda_bf16.h>
#include <cstdint>

#define BB   8192
#define TT   64
#define FF   64
#define ORD  16
#define KK   256            // hidden units
#define RTOT 336            // F + ORD + K
#define RPAD 352            // padded to 11 * 32
#define KC   32
#define NCH  11             // 352/32 k-chunks
#define MT   128            // rows per CTA
#define NT   256            // z-cols per CTA (64 units * 4 gates)
#define NTH  512

// smem: pitch 80B (64B data + 16 pad) -> conflict-free ldmatrix
#define ROWB    80
#define OFF_AH  0
#define OFF_AL  10240                  // 128*80
#define OFF_W   20480
#define WHL     20480                  // 256*80
#define BUFSZ   61440                  // A(2*10240) + W(2*20480)
#define NBUF    3
#define OFF_PART (NBUF * BUFSZ)        // 184320
#define SMEM_TOTAL (OFF_PART + 128 * 4 * 4 + 256)

// ---------------- persistent device state ----------------
__device__ __align__(16) __nv_bfloat16 g_Xh[(size_t)BB * TT * FF];
__device__ __align__(16) __nv_bfloat16 g_Xl[(size_t)BB * TT * FF];
__device__ __align__(16) __nv_bfloat16 g_Hh[2][(size_t)BB * KK];
__device__ __align__(16) __nv_bfloat16 g_Hl[2][(size_t)BB * KK];
__device__ __align__(16) float g_c[(size_t)BB * KK];
__device__ __align__(16) __nv_bfloat16 g_YPh[BB * ORD];
__device__ __align__(16) __nv_bfloat16 g_YPl[BB * ORD];
__device__ __align__(16) __nv_bfloat16 g_Wth[1024 * RPAD];   // [n'=4u+g][k], zero-padded
__device__ __align__(16) __nv_bfloat16 g_Wtl[1024 * RPAD];
__device__ __align__(16) __nv_bfloat16 g_zero[8];            // zero-init .bss
__device__ float4 g_biasp[KK];
__device__ float  g_part[4 * BB];      // per-col-CTA partial dense dots

// ---------------- helpers ----------------
__device__ __forceinline__ uint32_t smem_u32(const void* p) {
    uint32_t a;
    asm("{ .reg .u64 t; cvta.to.shared.u64 t, %1; cvt.u32.u64 %0, t; }" : "=r"(a) : "l"(p));
    return a;
}
__device__ __forceinline__ void cpa16(uint32_t dst, const void* src) {
    asm volatile("cp.async.cg.shared.global [%0], [%1], 16;" :: "r"(dst), "l"(src) : "memory");
}
__device__ __forceinline__ void ldsm4(uint32_t (&r)[4], uint32_t a) {
    asm volatile("ldmatrix.sync.aligned.m8n8.x4.shared.b16 {%0,%1,%2,%3}, [%4];"
                 : "=r"(r[0]), "=r"(r[1]), "=r"(r[2]), "=r"(r[3]) : "r"(a));
}
__device__ __forceinline__ void mma16816(float (&d)[4], const uint32_t (&a)[4],
                                         uint32_t b0, uint32_t b1) {
    asm volatile("mma.sync.aligned.m16n8k16.row.col.f32.bf16.bf16.f32 "
                 "{%0,%1,%2,%3}, {%4,%5,%6,%7}, {%8,%9}, {%0,%1,%2,%3};"
                 : "+f"(d[0]), "+f"(d[1]), "+f"(d[2]), "+f"(d[3])
                 : "r"(a[0]), "r"(a[1]), "r"(a[2]), "r"(a[3]), "r"(b0), "r"(b1));
}
__device__ __forceinline__ float sigm(float x) { return 1.0f / (1.0f + __expf(-x)); }
__device__ __forceinline__ float tanh_(float x) {
    float e = __expf(2.0f * x);
    return 1.0f - 2.0f / (e + 1.0f);
}
__device__ __forceinline__ void split_bf16(float v, __nv_bfloat16& hi, __nv_bfloat16& lo) {
    hi = __float2bfloat16(v);
    lo = __float2bfloat16(v - __bfloat162float(hi));
}

// ---------------- setup kernels ----------------
__global__ void conv_x_kernel(const float* __restrict__ x) {
    size_t n = (size_t)BB * TT * FF;
    for (size_t i = (size_t)blockIdx.x * blockDim.x + threadIdx.x; i < n;
         i += (size_t)gridDim.x * blockDim.x) {
        __nv_bfloat16 h, l;
        split_bf16(x[i], h, l);
        g_Xh[i] = h; g_Xl[i] = l;
    }
}
__global__ void init_state_kernel(const float* __restrict__ y0) {
    int i = blockIdx.x * blockDim.x + threadIdx.x;
    int st = gridDim.x * blockDim.x;
    __nv_bfloat16 z = __float2bfloat16(0.0f);
    for (size_t s = i; s < (size_t)BB * KK; s += st) {
        g_c[s] = 0.0f;
        g_Hh[0][s] = z; g_Hl[0][s] = z;
        g_Hh[1][s] = z; g_Hl[1][s] = z;
    }
    for (int s = i; s < BB * ORD; s += st) {
        __nv_bfloat16 h, l;
        split_bf16(y0[s], h, l);
        g_YPh[s] = h; g_YPl[s] = l;
    }
}
__global__ void repack_w_kernel(const float* __restrict__ kern,  // [80,1024]
                                const float* __restrict__ rec,   // [256,1024]
                                const float* __restrict__ bias) {
    int i = blockIdx.x * blockDim.x + threadIdx.x;
    int st = gridDim.x * blockDim.x;
    for (int idx = i; idx < 1024 * RPAD; idx += st) {
        int np = idx / RPAD;
        int k  = idx - np * RPAD;
        int u = np >> 2, g = np & 3;
        int col = g * 256 + u;                  // Keras gate order i,f,c,o
        float v = 0.0f;
        if (k < FF + ORD)      v = kern[k * 1024 + col];
        else if (k < RTOT)     v = rec[(k - 80) * 1024 + col];
        __nv_bfloat16 h, l;
        split_bf16(v, h, l);
        g_Wth[idx] = h; g_Wtl[idx] = l;
    }
    for (int u = i; u < KK; u += st) {
        float4 b;
        b.x = bias[u]; b.y = bias[256 + u]; b.z = bias[512 + u]; b.w = bias[768 + u];
        g_biasp[u] = b;
    }
}

// ---------------- fused timestep: HMMA GEMM + gates + partial dense ---------
// grid (64, 4), 512 threads. Warp tile 32 rows x 64 cols. acc fp32.
__global__ void __launch_bounds__(NTH, 1)
lstm_step(int t, int par, const float* __restrict__ dw) {
    extern __shared__ __align__(16) char sm[];
    const uint32_t sb = smem_u32(sm);
    const int tid  = threadIdx.x;
    const int wid  = tid >> 5;
    const int lane = tid & 31;
    const int g8   = lane >> 2;
    const int tid4 = lane & 3;
    const int warpM = wid & 3;
    const int warpN = wid >> 2;
    const int mrow0 = blockIdx.x * MT;
    const int ncol0 = blockIdx.y * NT;

    const __nv_bfloat16* __restrict__ Hh = g_Hh[par];
    const __nv_bfloat16* __restrict__ Hl = g_Hl[par];

    // --- staging: one k32 chunk into buffer b ---
    auto stage = [&](int kc, int b) {
        const uint32_t bufb = sb + b * BUFSZ;
        // A: 128 rows x 4 halves x {hi,lo} = 1024 jobs, 2 per thread
        #pragma unroll
        for (int i = 0; i < 2; i++) {
            int job  = tid + i * NTH;
            int row  = job >> 3;
            int half = job & 3;
            int hilo = (job >> 2) & 1;
            int kg   = kc * KC + half * 8;
            int grow = mrow0 + row;
            const __nv_bfloat16* src;
            if (kg < 64)
                src = (hilo ? g_Xl : g_Xh) + (size_t)grow * (TT * FF) + t * FF + kg;
            else if (kg < 80)
                src = (hilo ? g_YPl : g_YPh) + grow * ORD + (kg - 64);
            else if (kg < RTOT)
                src = (hilo ? Hl : Hh) + (size_t)grow * KK + (kg - 80);
            else
                src = g_zero;
            cpa16(bufb + (hilo ? OFF_AL : OFF_AH) + row * ROWB + half * 16, src);
        }
        // W: 256 rows x 4 halves x {hi,lo} = 2048 jobs, 4 per thread
        #pragma unroll
        for (int i = 0; i < 4; i++) {
            int job  = tid + i * NTH;
            int n    = job >> 3;
            int half = job & 3;
            int hilo = (job >> 2) & 1;
            const __nv_bfloat16* src =
                (hilo ? g_Wtl : g_Wth) + (size_t)(ncol0 + n) * RPAD + kc * KC + half * 8;
            cpa16(bufb + OFF_W + hilo * WHL + n * ROWB + half * 16, src);
        }
        asm volatile("cp.async.commit_group;" ::: "memory");
    };

    float acc[2][8][4];
    #pragma unroll
    for (int mi = 0; mi < 2; mi++)
        #pragma unroll
        for (int nj = 0; nj < 8; nj++)
            #pragma unroll
            for (int q = 0; q < 4; q++) acc[mi][nj][q] = 0.0f;

    const int lrow = lane & 15;
    const int lcol16 = (lane >> 4) * 16;
    const uint32_t aoff = (uint32_t)(warpM * 32 + lrow) * ROWB + lcol16;
    const uint32_t woff = (uint32_t)(warpN * 64 + lrow) * ROWB + lcol16;

    stage(0, 0);
    int bufidx = 0;
    for (int kc = 0; kc < NCH; kc++) {
        if (kc + 1 < NCH) {
            int nb3 = bufidx + 1; if (nb3 == NBUF) nb3 = 0;
            stage(kc + 1, nb3);
            asm volatile("cp.async.wait_group 1;" ::: "memory");
        } else {
            asm volatile("cp.async.wait_group 0;" ::: "memory");
        }
        __syncthreads();

        const uint32_t bufb = sb + bufidx * BUFSZ;
        #pragma unroll
        for (int k16 = 0; k16 < 2; k16++) {
            const uint32_t kofs = k16 * 32;
            uint32_t ah[2][4], al[2][4];
            #pragma unroll
            for (int mi = 0; mi < 2; mi++) {
                ldsm4(ah[mi], bufb + OFF_AH + aoff + mi * (16 * ROWB) + kofs);
                ldsm4(al[mi], bufb + OFF_AL + aoff + mi * (16 * ROWB) + kofs);
            }
            #pragma unroll
            for (int nb = 0; nb < 4; nb++) {
                uint32_t wh[4], wl[4];
                ldsm4(wh, bufb + OFF_W + woff + nb * (16 * ROWB) + kofs);
                ldsm4(wl, bufb + OFF_W + WHL + woff + nb * (16 * ROWB) + kofs);
                #pragma unroll
                for (int mi = 0; mi < 2; mi++) {
                    mma16816(acc[mi][2 * nb + 0], ah[mi], wh[0], wh[2]);
                    mma16816(acc[mi][2 * nb + 1], ah[mi], wh[1], wh[3]);
                    mma16816(acc[mi][2 * nb + 0], al[mi], wh[0], wh[2]);
                    mma16816(acc[mi][2 * nb + 1], al[mi], wh[1], wh[3]);
                    mma16816(acc[mi][2 * nb + 0], ah[mi], wl[0], wl[2]);
                    mma16816(acc[mi][2 * nb + 1], ah[mi], wl[1], wl[3]);
                }
            }
        }
        bufidx++; if (bufidx == NBUF) bufidx = 0;
    }

    // ---- epilogue: gates, state update, partial dense dot ----
    __nv_bfloat16* __restrict__ Hho = g_Hh[par ^ 1];
    __nv_bfloat16* __restrict__ Hlo = g_Hl[par ^ 1];
    float rd[4] = {0.0f, 0.0f, 0.0f, 0.0f};
    const bool evenlane = ((tid4 & 1) == 0);

    #pragma unroll
    for (int mi = 0; mi < 2; mi++) {
        #pragma unroll
        for (int nj = 0; nj < 8; nj++) {
            float c0 = acc[mi][nj][0], c1 = acc[mi][nj][1];
            float c2 = acc[mi][nj][2], c3 = acc[mi][nj][3];
            float o0 = __shfl_xor_sync(0xffffffffu, c0, 1);
            float o1 = __shfl_xor_sync(0xffffffffu, c1, 1);
            float o2 = __shfl_xor_sync(0xffffffffu, c2, 1);
            float o3 = __shfl_xor_sync(0xffffffffu, c3, 1);
            if (evenlane) {
                const int u = ((ncol0 + warpN * 64 + nj * 8) >> 2) + (tid4 >> 1);
                const float4 bp = g_biasp[u];
                const float dwu = dw[u];
                const int r0 = mrow0 + warpM * 32 + mi * 16 + g8;
                #pragma unroll
                for (int rr = 0; rr < 2; rr++) {
                    const float zi = rr ? c2 : c0;
                    const float zf = rr ? c3 : c1;
                    const float zg = rr ? o2 : o0;
                    const float zo = rr ? o3 : o1;
                    const int row = r0 + rr * 8;
                    const size_t off = (size_t)row * KK + u;
                    float gi = sigm(zi + bp.x);
                    float gf = sigm(zf + bp.y);
                    float gg = tanh_(zg + bp.z);
                    float go = sigm(zo + bp.w);
                    float cn = gf * g_c[off] + gi * gg;
                    g_c[off] = cn;
                    float hn = go * tanh_(cn);
                    __nv_bfloat16 hh, hl;
                    split_bf16(hn, hh, hl);
                    Hho[off] = hh;
                    Hlo[off] = hl;
                    rd[mi * 2 + rr] += hn * dwu;
                }
            }
        }
    }
    #pragma unroll
    for (int q = 0; q < 4; q++)
        rd[q] += __shfl_xor_sync(0xffffffffu, rd[q], 2);

    float* part = (float*)(sm + OFF_PART);   // [128][4]
    if (tid4 == 0) {
        #pragma unroll
        for (int mi = 0; mi < 2; mi++)
            #pragma unroll
            for (int rr = 0; rr < 2; rr++)
                part[(warpM * 32 + mi * 16 + g8 + rr * 8) * 4 + warpN] = rd[mi * 2 + rr];
    }
    __syncthreads();
    if (tid < 128) {
        float s = part[tid * 4 + 0] + part[tid * 4 + 1] +
                  part[tid * 4 + 2] + part[tid * 4 + 3];
        g_part[blockIdx.y * BB + mrow0 + tid] = s;
    }
}

// ---------------- finalize: sum partials, emit pred, shift window -----------
__global__ void finalize_kernel(float* __restrict__ out,
                                const float* __restrict__ db, int t) {
    const int row = blockIdx.x * blockDim.x + threadIdx.x;
    if (row >= BB) return;
    float p = g_part[row] + g_part[BB + row] + g_part[2 * BB + row] +
              g_part[3 * BB + row] + db[0];
    out[(size_t)row * TT + t] = p;

    __nv_bfloat16* yph = g_YPh + row * ORD;
    __nv_bfloat16* ypl = g_YPl + row * ORD;
    __nv_bfloat16 th[ORD], tl[ORD];
    #pragma unroll
    for (int i = 0; i < ORD; i++) { th[i] = yph[i]; tl[i] = ypl[i]; }
    #pragma unroll
    for (int i = ORD - 1; i >= 1; i--) { yph[i] = th[i - 1]; ypl[i] = tl[i - 1]; }
    __nv_bfloat16 ph, pl;
    split_bf16(p, ph, pl);
    yph[0] = ph; ypl[0] = pl;
}

// ---------------- launch ----------------
extern "C" void kernel_launch(void* const* d_in, const int* in_sizes, int n_in,
                              void* d_out, int out_size) {
    const float* x    = (const float*)d_in[0];
    const float* y0   = (const float*)d_in[1];
    const float* kern = (const float*)d_in[2];
    const float* rec  = (const float*)d_in[3];
    const float* bias = (const float*)d_in[4];
    const float* dw   = (const float*)d_in[5];
    const float* db   = (const float*)d_in[6];
    float* out = (float*)d_out;

    cudaFuncSetAttribute(lstm_step,
                         cudaFuncAttributeMaxDynamicSharedMemorySize, SMEM_TOTAL);

    conv_x_kernel<<<2048, 256>>>(x);
    init_state_kernel<<<1024, 256>>>(y0);
    repack_w_kernel<<<1024, 256>>>(kern, rec, bias);

    dim3 grid(BB / MT, 4);   // (64, 4)
    for (int t = 0; t < TT; t++) {
        lstm_step<<<grid, NTH, SMEM_TOTAL>>>(t, t & 1, dw);
        finalize_kernel<<<BB / 256, 256>>>(out, db, t);
    }
}

// round 9
// speedup vs baseline: 1.0624x; 1.0624x over previous
#include <cuda_runtime.h>
#include <cuda_bf16.h>
#include <cstdint>

#define BB   8192
#define TT   64
#define FF   64
#define ORD  16
#define KK   256            // hidden units
#define RTOT 336            // F + ORD + K
#define NCH  21             // 336/16 k-chunks
#define MT   64             // rows per CTA
#define NT   256            // z-cols per CTA (64 units * 4 gates)
#define NTH  256

// smem: staged tiles, rows padded to 48B for conflict-free ldmatrix
#define ROWB   48
#define OFF_AH 0
#define OFF_AL (64 * ROWB)             // 3072
#define OFF_WH (2 * 64 * ROWB)         // 6144
#define OFF_WL (OFF_WH + 256 * ROWB)   // 18432
#define BUFSZ  (OFF_WL + 256 * ROWB)   // 30720
#define OFF_PART (2 * BUFSZ)           // 61440, 64x4 floats
#define SMEM_TOTAL (OFF_PART + 64 * 4 * 4 + 256)

// ---------------- persistent device state ----------------
__device__ __align__(16) __nv_bfloat16 g_Xh[(size_t)BB * TT * FF];
__device__ __align__(16) __nv_bfloat16 g_Xl[(size_t)BB * TT * FF];
__device__ __align__(16) __nv_bfloat16 g_Hh[2][(size_t)BB * KK];
__device__ __align__(16) __nv_bfloat16 g_Hl[2][(size_t)BB * KK];
__device__ __align__(16) float g_c[(size_t)BB * KK];
__device__ __align__(16) __nv_bfloat16 g_YPh[BB * ORD];
__device__ __align__(16) __nv_bfloat16 g_YPl[BB * ORD];
__device__ __align__(16) __nv_bfloat16 g_Wth[1024 * RTOT];   // [n'=4u+g][k]
__device__ __align__(16) __nv_bfloat16 g_Wtl[1024 * RTOT];
__device__ float4 g_biasp[KK];
__device__ float  g_part[4 * BB];      // per-col-CTA partial dense dots

// ---------------- helpers ----------------
__device__ __forceinline__ uint32_t smem_u32(const void* p) {
    uint32_t a;
    asm("{ .reg .u64 t; cvta.to.shared.u64 t, %1; cvt.u32.u64 %0, t; }" : "=r"(a) : "l"(p));
    return a;
}
__device__ __forceinline__ void cpa16(uint32_t dst, const void* src) {
    asm volatile("cp.async.cg.shared.global [%0], [%1], 16;" :: "r"(dst), "l"(src) : "memory");
}
__device__ __forceinline__ void ldsm4(uint32_t (&r)[4], uint32_t a) {
    asm volatile("ldmatrix.sync.aligned.m8n8.x4.shared.b16 {%0,%1,%2,%3}, [%4];"
                 : "=r"(r[0]), "=r"(r[1]), "=r"(r[2]), "=r"(r[3]) : "r"(a));
}
__device__ __forceinline__ void mma16816(float (&d)[4], const uint32_t (&a)[4],
                                         uint32_t b0, uint32_t b1) {
    asm volatile("mma.sync.aligned.m16n8k16.row.col.f32.bf16.bf16.f32 "
                 "{%0,%1,%2,%3}, {%4,%5,%6,%7}, {%8,%9}, {%0,%1,%2,%3};"
                 : "+f"(d[0]), "+f"(d[1]), "+f"(d[2]), "+f"(d[3])
                 : "r"(a[0]), "r"(a[1]), "r"(a[2]), "r"(a[3]), "r"(b0), "r"(b1));
}
__device__ __forceinline__ float sigm(float x) { return 1.0f / (1.0f + __expf(-x)); }
__device__ __forceinline__ float tanh_(float x) {
    float e = __expf(2.0f * x);
    return 1.0f - 2.0f / (e + 1.0f);
}
__device__ __forceinline__ void split_bf16(float v, __nv_bfloat16& hi, __nv_bfloat16& lo) {
    hi = __float2bfloat16(v);
    lo = __float2bfloat16(v - __bfloat162float(hi));
}

// ---------------- setup kernels ----------------
__global__ void conv_x_kernel(const float* __restrict__ x) {
    size_t n = (size_t)BB * TT * FF;
    for (size_t i = (size_t)blockIdx.x * blockDim.x + threadIdx.x; i < n;
         i += (size_t)gridDim.x * blockDim.x) {
        __nv_bfloat16 h, l;
        split_bf16(x[i], h, l);
        g_Xh[i] = h; g_Xl[i] = l;
    }
}
__global__ void init_state_kernel(const float* __restrict__ y0) {
    int i = blockIdx.x * blockDim.x + threadIdx.x;
    int st = gridDim.x * blockDim.x;
    __nv_bfloat16 z = __float2bfloat16(0.0f);
    for (size_t s = i; s < (size_t)BB * KK; s += st) {
        g_c[s] = 0.0f;
        g_Hh[0][s] = z; g_Hl[0][s] = z;
        g_Hh[1][s] = z; g_Hl[1][s] = z;
    }
    for (int s = i; s < BB * ORD; s += st) {
        __nv_bfloat16 h, l;
        split_bf16(y0[s], h, l);
        g_YPh[s] = h; g_YPl[s] = l;
    }
}
__global__ void repack_w_kernel(const float* __restrict__ kern,  // [80,1024]
                                const float* __restrict__ rec,   // [256,1024]
                                const float* __restrict__ bias) {
    int i = blockIdx.x * blockDim.x + threadIdx.x;
    int st = gridDim.x * blockDim.x;
    for (int idx = i; idx < 1024 * RTOT; idx += st) {
        int np = idx / RTOT;
        int k  = idx - np * RTOT;
        int u = np >> 2, g = np & 3;
        int col = g * 256 + u;                  // Keras gate order i,f,c,o
        float v = (k < FF + ORD) ? kern[k * 1024 + col] : rec[(k - 80) * 1024 + col];
        __nv_bfloat16 h, l;
        split_bf16(v, h, l);
        g_Wth[idx] = h; g_Wtl[idx] = l;
    }
    for (int u = i; u < KK; u += st) {
        float4 b;
        b.x = bias[u]; b.y = bias[256 + u]; b.z = bias[512 + u]; b.w = bias[768 + u];
        g_biasp[u] = b;
    }
}

// ---------------- fused timestep: HMMA GEMM + gates + partial dense ---------
// grid (128, 4), 256 threads, 2 CTAs/SM. Warp tile 32 rows x 64 cols.
__global__ void __launch_bounds__(NTH, 2)
lstm_step(int t, int par, const float* __restrict__ dw) {
    extern __shared__ __align__(16) char sm[];
    const uint32_t sb = smem_u32(sm);
    const int tid  = threadIdx.x;
    const int wid  = tid >> 5;
    const int lane = tid & 31;
    const int g8   = lane >> 2;
    const int tid4 = lane & 3;
    const int warpM = wid & 1;       // 2 row groups * 32 rows
    const int warpN = wid >> 1;      // 4 col groups * 64 cols
    const int mrow0 = blockIdx.x * MT;
    const int ncol0 = blockIdx.y * NT;

    const __nv_bfloat16* __restrict__ Hh = g_Hh[par];
    const __nv_bfloat16* __restrict__ Hl = g_Hl[par];

    // --- staging: one k16 chunk into buffer b ---
    auto stage = [&](int kc, int b) {
        uint32_t bufb = sb + b * BUFSZ;
        // A: 64 rows x {hi,lo} x {k8 halves} = 256 jobs, 1 per thread
        {
            int row  = tid >> 2;
            int half = tid & 1;
            int hilo = (tid >> 1) & 1;
            int kg   = kc * 16 + half * 8;
            int grow = mrow0 + row;
            const __nv_bfloat16* src;
            if (kg < 64)
                src = (hilo ? g_Xl : g_Xh) + (size_t)grow * (TT * FF) + t * FF + kg;
            else if (kg < 80)
                src = (hilo ? g_YPl : g_YPh) + grow * ORD + (kg - 64);
            else
                src = (hilo ? Hl : Hh) + (size_t)grow * KK + (kg - 80);
            cpa16(bufb + (hilo ? OFF_AL : OFF_AH) + row * ROWB + half * 16, src);
        }
        // W: 256 n-rows x {hi,lo} x {halves} = 1024 jobs, 4 per thread
        #pragma unroll
        for (int j = 0; j < 4; j++) {
            int idx  = tid + j * NTH;
            int n    = idx >> 2;
            int half = idx & 1;
            int hilo = (idx >> 1) & 1;
            const __nv_bfloat16* src =
                (hilo ? g_Wtl : g_Wth) + (size_t)(ncol0 + n) * RTOT + kc * 16 + half * 8;
            cpa16(bufb + (hilo ? OFF_WL : OFF_WH) + n * ROWB + half * 16, src);
        }
        asm volatile("cp.async.commit_group;" ::: "memory");
    };

    float acc[2][8][4];
    #pragma unroll
    for (int mi = 0; mi < 2; mi++)
        #pragma unroll
        for (int nj = 0; nj < 8; nj++)
            #pragma unroll
            for (int q = 0; q < 4; q++) acc[mi][nj][q] = 0.0f;

    stage(0, 0);
    const int lrow = lane & 15;
    const int lcol16 = (lane >> 4) * 16;
    const uint32_t aoff = (uint32_t)(warpM * 32 + lrow) * ROWB + lcol16;
    const uint32_t woff = (uint32_t)(warpN * 64 + lrow) * ROWB + lcol16;

    for (int kc = 0; kc < NCH; kc++) {
        if (kc + 1 < NCH) {
            stage(kc + 1, (kc + 1) & 1);
            asm volatile("cp.async.wait_group 1;" ::: "memory");
        } else {
            asm volatile("cp.async.wait_group 0;" ::: "memory");
        }
        __syncthreads();

        const uint32_t bufb = sb + (kc & 1) * BUFSZ;
        uint32_t ah[2][4], al[2][4];
        #pragma unroll
        for (int mi = 0; mi < 2; mi++) {
            ldsm4(ah[mi], bufb + OFF_AH + aoff + mi * (16 * ROWB));
            ldsm4(al[mi], bufb + OFF_AL + aoff + mi * (16 * ROWB));
        }
        #pragma unroll
        for (int nb = 0; nb < 4; nb++) {
            uint32_t wh[4], wl[4];
            ldsm4(wh, bufb + OFF_WH + woff + nb * (16 * ROWB));
            ldsm4(wl, bufb + OFF_WL + woff + nb * (16 * ROWB));
            // product-outermost ordering: same-acc reuse distance = 4 MMAs
            #pragma unroll
            for (int p = 0; p < 3; p++) {
                const uint32_t* aa = (p == 1) ? &al[0][0] : &ah[0][0];
                const uint32_t* ww = (p == 2) ? wl : wh;
                #pragma unroll
                for (int mi = 0; mi < 2; mi++) {
                    const uint32_t (&af)[4] = *(const uint32_t (*)[4])(aa + mi * 4);
                    mma16816(acc[mi][2 * nb + 0], af, ww[0], ww[2]);
                    mma16816(acc[mi][2 * nb + 1], af, ww[1], ww[3]);
                }
            }
        }
        __syncthreads();
    }

    // ---- epilogue: gates, state update, partial dense dot ----
    __nv_bfloat16* __restrict__ Hho = g_Hh[par ^ 1];
    __nv_bfloat16* __restrict__ Hlo = g_Hl[par ^ 1];
    float rd[4] = {0.0f, 0.0f, 0.0f, 0.0f};
    const bool evenlane = ((tid4 & 1) == 0);

    #pragma unroll
    for (int mi = 0; mi < 2; mi++) {
        #pragma unroll
        for (int nj = 0; nj < 8; nj++) {
            float c0 = acc[mi][nj][0], c1 = acc[mi][nj][1];
            float c2 = acc[mi][nj][2], c3 = acc[mi][nj][3];
            float o0 = __shfl_xor_sync(0xffffffffu, c0, 1);
            float o1 = __shfl_xor_sync(0xffffffffu, c1, 1);
            float o2 = __shfl_xor_sync(0xffffffffu, c2, 1);
            float o3 = __shfl_xor_sync(0xffffffffu, c3, 1);
            if (evenlane) {
                const int u = ((ncol0 + warpN * 64 + nj * 8) >> 2) + (tid4 >> 1);
                const float4 bp = g_biasp[u];
                const float dwu = dw[u];
                const int r0 = mrow0 + warpM * 32 + mi * 16 + g8;
                #pragma unroll
                for (int rr = 0; rr < 2; rr++) {
                    const float zi = rr ? c2 : c0;
                    const float zf = rr ? c3 : c1;
                    const float zg = rr ? o2 : o0;
                    const float zo = rr ? o3 : o1;
                    const int row = r0 + rr * 8;
                    const size_t off = (size_t)row * KK + u;
                    float gi = sigm(zi + bp.x);
                    float gf = sigm(zf + bp.y);
                    float gg = tanh_(zg + bp.z);
                    float go = sigm(zo + bp.w);
                    float cn = gf * g_c[off] + gi * gg;
                    g_c[off] = cn;
                    float hn = go * tanh_(cn);
                    __nv_bfloat16 hh, hl;
                    split_bf16(hn, hh, hl);
                    Hho[off] = hh;
                    Hlo[off] = hl;
                    rd[mi * 2 + rr] += hn * dwu;
                }
            }
        }
    }
    #pragma unroll
    for (int q = 0; q < 4; q++)
        rd[q] += __shfl_xor_sync(0xffffffffu, rd[q], 2);

    float* part = (float*)(sm + OFF_PART);   // [64][4]
    if (tid4 == 0) {
        #pragma unroll
        for (int mi = 0; mi < 2; mi++)
            #pragma unroll
            for (int rr = 0; rr < 2; rr++)
                part[(warpM * 32 + mi * 16 + g8 + rr * 8) * 4 + warpN] = rd[mi * 2 + rr];
    }
    __syncthreads();
    if (tid < 64) {
        float s = part[tid * 4 + 0] + part[tid * 4 + 1] +
                  part[tid * 4 + 2] + part[tid * 4 + 3];
        g_part[blockIdx.y * BB + mrow0 + tid] = s;
    }
}

// ---------------- finalize: sum partials, emit pred, shift window -----------
__global__ void finalize_kernel(float* __restrict__ out,
                                const float* __restrict__ db, int t) {
    const int row = blockIdx.x * blockDim.x + threadIdx.x;
    if (row >= BB) return;
    float p = g_part[row] + g_part[BB + row] + g_part[2 * BB + row] +
              g_part[3 * BB + row] + db[0];
    out[(size_t)row * TT + t] = p;

    __nv_bfloat16* yph = g_YPh + row * ORD;
    __nv_bfloat16* ypl = g_YPl + row * ORD;
    __nv_bfloat16 th[ORD], tl[ORD];
    #pragma unroll
    for (int i = 0; i < ORD; i++) { th[i] = yph[i]; tl[i] = ypl[i]; }
    #pragma unroll
    for (int i = ORD - 1; i >= 1; i--) { yph[i] = th[i - 1]; ypl[i] = tl[i - 1]; }
    __nv_bfloat16 ph, pl;
    split_bf16(p, ph, pl);
    yph[0] = ph; ypl[0] = pl;
}

// ---------------- launch ----------------
extern "C" void kernel_launch(void* const* d_in, const int* in_sizes, int n_in,
                              void* d_out, int out_size) {
    const float* x    = (const float*)d_in[0];
    const float* y0   = (const float*)d_in[1];
    const float* kern = (const float*)d_in[2];
    const float* rec  = (const float*)d_in[3];
    const float* bias = (const float*)d_in[4];
    const float* dw   = (const float*)d_in[5];
    const float* db   = (const float*)d_in[6];
    float* out = (float*)d_out;

    cudaFuncSetAttribute(lstm_step,
                         cudaFuncAttributeMaxDynamicSharedMemorySize, SMEM_TOTAL);

    conv_x_kernel<<<2048, 256>>>(x);
    init_state_kernel<<<1024, 256>>>(y0);
    repack_w_kernel<<<1024, 256>>>(kern, rec, bias);

    dim3 grid(BB / MT, 4);   // (128, 4)
    for (int t = 0; t < TT; t++) {
        lstm_step<<<grid, NTH, SMEM_TOTAL>>>(t, t & 1, dw);
        finalize_kernel<<<BB / 256, 256>>>(out, db, t);
    }
}